// round 7
// baseline (speedup 1.0000x reference)
#include <cuda_runtime.h>
#include <cstdint>

#define NN 50000
#define NE 800000
#define NG 64
#define EPSV 1e-5f

// ---------------- scratch (device globals; no allocations allowed) ----------------
__device__ float g_bufA[NN * 256];
__device__ float g_bufB[NN * 256];
__device__ float g_dinv[NN];
__device__ __align__(16) int g_deg[NN + 8];
__device__ __align__(16) int g_rowstart[NN + 8];
__device__ int   g_fill[NN];
__device__ int   g_csr[NE];
__device__ float g_bnsum[192];
__device__ float g_bnsq[192];
__device__ float g_a[192];   // [0:128) bn1 scale, [128:192) bn2 scale (bn2 unused globally now)
__device__ float g_c[192];
__device__ float g_pool[NG * 64];
__device__ int   g_cnt[NG];
__device__ int   g_ctr[4];

// ---------------- TF32 helpers ----------------
__device__ __forceinline__ unsigned cvt_tf32(float v) {
    unsigned r;
    asm("cvt.rna.tf32.f32 %0, %1;" : "=r"(r) : "f"(v));
    return r;
}
__device__ __forceinline__ void mma_tf32(float* c, const unsigned* a, const unsigned* b) {
    asm volatile(
        "mma.sync.aligned.m16n8k8.row.col.f32.tf32.tf32.f32 "
        "{%0,%1,%2,%3}, {%4,%5,%6,%7}, {%8,%9}, {%0,%1,%2,%3};"
        : "+f"(c[0]), "+f"(c[1]), "+f"(c[2]), "+f"(c[3])
        : "r"(a[0]), "r"(a[1]), "r"(a[2]), "r"(a[3]), "r"(b[0]), "r"(b[1]));
}

__device__ __forceinline__ float4 f4add(float4 a, float4 b) {
    return make_float4(a.x + b.x, a.y + b.y, a.z + b.z, a.w + b.w);
}
__device__ __forceinline__ float4 f4sq(float4 a) {
    return make_float4(a.x * a.x, a.y * a.y, a.z * a.z, a.w * a.w);
}

// ---------------- setup kernels ----------------
__global__ void zero_kernel() {
    int i = blockIdx.x * 256 + threadIdx.x;
    if (i < NN) g_deg[i] = 0;
    if (i < 192) { g_bnsum[i] = 0.f; g_bnsq[i] = 0.f; }
    if (i < NG * 64) g_pool[i] = 0.f;
    if (i < NG) g_cnt[i] = 0;
    if (i < 4) g_ctr[i] = 0;
}

__global__ void count_kernel(const int* __restrict__ dst) {
    int e = (blockIdx.x * 256 + threadIdx.x) * 2;
    if (e < NE) {
        int2 d = *(const int2*)&dst[e];
        atomicAdd(&g_deg[d.x], 1);
        atomicAdd(&g_deg[d.y], 1);
    }
}

// Single-block exclusive scan over degrees -> rowstart (int4-vectorized).
__global__ void scan_kernel() {
    const int CH = 52;
    int tid = threadIdx.x;
    int lo = tid * CH; if (lo > NN) lo = NN;
    int hi = lo + CH;  if (hi > NN) hi = NN;
    int s = 0;
    for (int i = lo; i < hi; i += 4) {
        int4 d = *(const int4*)&g_deg[i];
        s += d.x + d.y + d.z + d.w;
    }
    __shared__ int warpsum[32];
    int lane = tid & 31, wid = tid >> 5;
    int incl = s;
    #pragma unroll
    for (int o = 1; o < 32; o <<= 1) {
        int v = __shfl_up_sync(0xffffffffu, incl, o);
        if (lane >= o) incl += v;
    }
    if (lane == 31) warpsum[wid] = incl;
    __syncthreads();
    if (wid == 0) {
        int w = warpsum[lane];
        int wincl = w;
        #pragma unroll
        for (int o = 1; o < 32; o <<= 1) {
            int v = __shfl_up_sync(0xffffffffu, wincl, o);
            if (lane >= o) wincl += v;
        }
        warpsum[lane] = wincl - w;
    }
    __syncthreads();
    int run = (incl - s) + warpsum[wid];
    for (int i = lo; i < hi; i += 4) {
        int4 d = *(const int4*)&g_deg[i];
        int4 rs;
        rs.x = run;
        rs.y = run + d.x;
        rs.z = run + d.x + d.y;
        rs.w = run + d.x + d.y + d.z;
        run += d.x + d.y + d.z + d.w;
        *(int4*)&g_rowstart[i] = rs;
    }
    if (lo < NN && hi == NN) g_rowstart[NN] = run;
}

// full-chip: dinv + fill cursors + per-graph node counts
__global__ void prep_kernel(const int* __restrict__ batch) {
    int i = blockIdx.x * 256 + threadIdx.x;
    if (i < NN) {
        g_dinv[i] = rsqrtf((float)(g_deg[i] + 1));
        g_fill[i] = 0;
        atomicAdd(&g_cnt[batch[i]], 1);
    }
}

__global__ void fill_kernel(const int* __restrict__ src, const int* __restrict__ dst) {
    int e = (blockIdx.x * 256 + threadIdx.x) * 2;
    if (e < NE) {
        int2 d = *(const int2*)&dst[e];
        int2 sc = *(const int2*)&src[e];
        int p0 = g_rowstart[d.x] + atomicAdd(&g_fill[d.x], 1);
        g_csr[p0] = sc.x;
        int p1 = g_rowstart[d.y] + atomicAdd(&g_fill[d.y], 1);
        g_csr[p1] = sc.y;
    }
}

// ---------------- layer-1 input aggregation (width 5) ----------------
__global__ void agg0_kernel(const float* __restrict__ x, float* __restrict__ xa) {
    int t = blockIdx.x * 256 + threadIdx.x;
    if (t >= NN * 5) return;
    int node = t / 5, f = t - node * 5;
    float dn = g_dinv[node];
    float acc = x[t] * dn;
    int s = g_rowstart[node], e = g_rowstart[node + 1];
    for (int j = s; j < e; j++) {
        int src = g_csr[j];
        acc += __ldg(&x[src * 5 + f]) * __ldg(&g_dinv[src]);
    }
    xa[t] = dn * acc;
}

// h1 = relu(xa @ W1 + b1), [N,5] -> [N,256]
__global__ void gemm1_kernel(const float* __restrict__ xa, const float* __restrict__ W1,
                             const float* __restrict__ b1, float* __restrict__ h1) {
    __shared__ float w[5 * 256];
    __shared__ float bs[256];
    for (int i = threadIdx.x; i < 1280; i += 256) w[i] = W1[i];
    bs[threadIdx.x] = b1[threadIdx.x];
    __syncthreads();
    int idx = blockIdx.x * 256 + threadIdx.x;
    if (idx >= NN * 64) return;
    int node = idx >> 6;
    int c = (idx & 63) * 4;
    float xv[5];
    #pragma unroll
    for (int k = 0; k < 5; k++) xv[k] = xa[node * 5 + k];
    float4 acc = make_float4(bs[c], bs[c + 1], bs[c + 2], bs[c + 3]);
    #pragma unroll
    for (int k = 0; k < 5; k++) {
        acc.x = fmaf(xv[k], w[k * 256 + c + 0], acc.x);
        acc.y = fmaf(xv[k], w[k * 256 + c + 1], acc.y);
        acc.z = fmaf(xv[k], w[k * 256 + c + 2], acc.z);
        acc.w = fmaf(xv[k], w[k * 256 + c + 3], acc.w);
    }
    acc.x = fmaxf(acc.x, 0.f); acc.y = fmaxf(acc.y, 0.f);
    acc.z = fmaxf(acc.z, 0.f); acc.w = fmaxf(acc.w, 0.f);
    ((float4*)h1)[idx] = acc;
}

// ---------------- TF32 tensor-core GEMM ----------------
template <int BM, int BN, int BK, int WM, int WN>
__global__ void gemm_tf32_kernel(const float* __restrict__ A, const float* __restrict__ W,
                                 float* __restrict__ out, int M, int K, int N,
                                 const float* __restrict__ affA, const float* __restrict__ affC,
                                 const float* __restrict__ rowscale) {
    constexpr int WARPS_M = BM / WM;
    constexpr int WARPS_N = BN / WN;
    constexpr int THREADS = WARPS_M * WARPS_N * 32;
    constexpr int MT = WM / 16;
    constexpr int NT = WN / 8;

    __shared__ unsigned As[BK][BM + 4];
    __shared__ unsigned Bs[BK][BN + 4];

    int tid = threadIdx.x;
    int lane = tid & 31;
    int wid = tid >> 5;
    int warpM = wid % WARPS_M;
    int warpN = wid / WARPS_M;
    int g = lane >> 2;
    int t = lane & 3;
    int rowBase = blockIdx.y * BM;
    int colBase = blockIdx.x * BN;

    float acc[MT][NT][4];
    #pragma unroll
    for (int i = 0; i < MT; i++)
        #pragma unroll
        for (int j = 0; j < NT; j++)
            #pragma unroll
            for (int q = 0; q < 4; q++) acc[i][j][q] = 0.f;

    for (int k0 = 0; k0 < K; k0 += BK) {
        #pragma unroll
        for (int it = tid; it < BM * BK / 4; it += THREADS) {
            int m = it / (BK / 4);
            int kq = (it % (BK / 4)) * 4;
            int gr = rowBase + m;
            float4 v = make_float4(0.f, 0.f, 0.f, 0.f);
            if (gr < M) {
                v = *(const float4*)&A[gr * K + k0 + kq];
                if (affA) {
                    v.x = fmaf(v.x, affA[k0 + kq + 0], affC[k0 + kq + 0]);
                    v.y = fmaf(v.y, affA[k0 + kq + 1], affC[k0 + kq + 1]);
                    v.z = fmaf(v.z, affA[k0 + kq + 2], affC[k0 + kq + 2]);
                    v.w = fmaf(v.w, affA[k0 + kq + 3], affC[k0 + kq + 3]);
                }
            }
            As[kq + 0][m] = cvt_tf32(v.x);
            As[kq + 1][m] = cvt_tf32(v.y);
            As[kq + 2][m] = cvt_tf32(v.z);
            As[kq + 3][m] = cvt_tf32(v.w);
        }
        #pragma unroll
        for (int it = tid; it < BK * BN / 4; it += THREADS) {
            int k = it / (BN / 4);
            int nq = (it % (BN / 4)) * 4;
            float4 v = *(const float4*)&W[(k0 + k) * N + colBase + nq];
            Bs[k][nq + 0] = cvt_tf32(v.x);
            Bs[k][nq + 1] = cvt_tf32(v.y);
            Bs[k][nq + 2] = cvt_tf32(v.z);
            Bs[k][nq + 3] = cvt_tf32(v.w);
        }
        __syncthreads();
        #pragma unroll
        for (int kk = 0; kk < BK; kk += 8) {
            unsigned a[MT][4], b[NT][2];
            #pragma unroll
            for (int mt = 0; mt < MT; mt++) {
                int mb = warpM * WM + mt * 16;
                a[mt][0] = As[kk + t][mb + g];
                a[mt][1] = As[kk + t][mb + g + 8];
                a[mt][2] = As[kk + t + 4][mb + g];
                a[mt][3] = As[kk + t + 4][mb + g + 8];
            }
            #pragma unroll
            for (int nt = 0; nt < NT; nt++) {
                int nb = warpN * WN + nt * 8;
                b[nt][0] = Bs[kk + t][nb + g];
                b[nt][1] = Bs[kk + t + 4][nb + g];
            }
            #pragma unroll
            for (int mt = 0; mt < MT; mt++)
                #pragma unroll
                for (int nt = 0; nt < NT; nt++)
                    mma_tf32(acc[mt][nt], a[mt], b[nt]);
        }
        __syncthreads();
    }

    #pragma unroll
    for (int mt = 0; mt < MT; mt++) {
        int r0 = rowBase + warpM * WM + mt * 16 + g;
        int r1 = r0 + 8;
        float rs0 = (r0 < M) ? (rowscale ? rowscale[r0] : 1.f) : 0.f;
        float rs1 = (r1 < M) ? (rowscale ? rowscale[r1] : 1.f) : 0.f;
        #pragma unroll
        for (int nt = 0; nt < NT; nt++) {
            int col = colBase + warpN * WN + nt * 8 + 2 * t;
            if (r0 < M) {
                float2 v = make_float2(acc[mt][nt][0] * rs0, acc[mt][nt][1] * rs0);
                *(float2*)&out[r0 * N + col] = v;
            }
            if (r1 < M) {
                float2 v = make_float2(acc[mt][nt][2] * rs1, acc[mt][nt][3] * rs1);
                *(float2*)&out[r1 * N + col] = v;
            }
        }
    }
}

// ---------------- agg core: 4-chain CSR gather ----------------
template <int CH>
__device__ __forceinline__ float4 agg_gather(const float4* __restrict__ u4,
                                             int node, int lane) {
    float4 a0 = u4[node * CH + lane];   // self-loop
    float4 a1 = make_float4(0.f, 0.f, 0.f, 0.f);
    float4 a2 = make_float4(0.f, 0.f, 0.f, 0.f);
    float4 a3 = make_float4(0.f, 0.f, 0.f, 0.f);
    int s = g_rowstart[node];
    int e = g_rowstart[node + 1];
    int j = s;
    for (; j + 4 <= e; j += 4) {
        int s0 = __ldg(&g_csr[j]);
        int s1 = __ldg(&g_csr[j + 1]);
        int s2 = __ldg(&g_csr[j + 2]);
        int s3 = __ldg(&g_csr[j + 3]);
        float4 v0 = __ldg(&u4[s0 * CH + lane]);
        float4 v1 = __ldg(&u4[s1 * CH + lane]);
        float4 v2 = __ldg(&u4[s2 * CH + lane]);
        float4 v3 = __ldg(&u4[s3 * CH + lane]);
        a0 = f4add(a0, v0); a1 = f4add(a1, v1);
        a2 = f4add(a2, v2); a3 = f4add(a3, v3);
    }
    for (; j < e; j++) {
        float4 v = __ldg(&u4[__ldg(&g_csr[j]) * CH + lane]);
        a0 = f4add(a0, v);
    }
    return f4add(f4add(a0, a1), f4add(a2, a3));
}

// ---------------- agg<128> + bn1 stats + finalize (last block) ----------------
// h2[i] = relu(dinv[i]*(u[i]+sum)+b2); bn1 sums/sqs accumulated; last block -> g_a/g_c[0:128)
__global__ void agg128_bn_kernel(const float* __restrict__ u, const float* __restrict__ bias,
                                 float* __restrict__ out,
                                 const float* __restrict__ gamma, const float* __restrict__ beta) {
    constexpr int CH = 32;
    int tid = threadIdx.x;
    int node = blockIdx.x * 8 + (tid >> 5);   // NN % 8 == 0
    int lane = tid & 31;
    const float4* u4 = (const float4*)u;
    float4 acc = agg_gather<CH>(u4, node, lane);
    float d = g_dinv[node];
    float4 b = ((const float4*)bias)[lane];
    float4 o;
    o.x = fmaxf(fmaf(d, acc.x, b.x), 0.f);
    o.y = fmaxf(fmaf(d, acc.y, b.y), 0.f);
    o.z = fmaxf(fmaf(d, acc.z, b.z), 0.f);
    o.w = fmaxf(fmaf(d, acc.w, b.w), 0.f);
    ((float4*)out)[node * CH + lane] = o;

    // block-reduce bn sums across the 8 node-warps
    __shared__ float4 rs[256], rq[256];
    __shared__ bool isLast;
    rs[tid] = o; rq[tid] = f4sq(o);
    __syncthreads();
    if (tid < 128) { rs[tid] = f4add(rs[tid], rs[tid + 128]); rq[tid] = f4add(rq[tid], rq[tid + 128]); }
    __syncthreads();
    if (tid < 64)  { rs[tid] = f4add(rs[tid], rs[tid + 64]);  rq[tid] = f4add(rq[tid], rq[tid + 64]); }
    __syncthreads();
    if (tid < 32) {
        float4 s4 = f4add(rs[tid], rs[tid + 32]);
        float4 q4 = f4add(rq[tid], rq[tid + 32]);
        atomicAdd(&g_bnsum[tid * 4 + 0], s4.x); atomicAdd(&g_bnsum[tid * 4 + 1], s4.y);
        atomicAdd(&g_bnsum[tid * 4 + 2], s4.z); atomicAdd(&g_bnsum[tid * 4 + 3], s4.w);
        atomicAdd(&g_bnsq[tid * 4 + 0], q4.x);  atomicAdd(&g_bnsq[tid * 4 + 1], q4.y);
        atomicAdd(&g_bnsq[tid * 4 + 2], q4.z);  atomicAdd(&g_bnsq[tid * 4 + 3], q4.w);
    }
    __threadfence();
    __syncthreads();
    if (tid == 0) isLast = (atomicAdd(&g_ctr[0], 1) == (int)gridDim.x - 1);
    __syncthreads();
    if (isLast && tid < 128) {
        float mean = g_bnsum[tid] * (1.0f / NN);
        float var = g_bnsq[tid] * (1.0f / NN) - mean * mean;
        float aa = gamma[tid] * rsqrtf(var + EPSV);
        g_a[tid] = aa;
        g_c[tid] = beta[tid] - mean * aa;
    }
}

// ---------------- agg<64> terminal: bn2 stats + pool + FC head; h3 never stored ----------------
__global__ void agg64_final_kernel(const float* __restrict__ u, const float* __restrict__ bias,
                                   const int* __restrict__ batch,
                                   const float* __restrict__ gamma2, const float* __restrict__ beta2,
                                   const float* __restrict__ Wfc, const float* __restrict__ bfc,
                                   float* __restrict__ outp) {
    constexpr int CH = 16;
    int tid = threadIdx.x;
    int node = blockIdx.x * 16 + (tid >> 4);   // NN % 16 == 0
    int lane = tid & 15;
    const float4* u4 = (const float4*)u;
    float4 acc = agg_gather<CH>(u4, node, lane);
    float d = g_dinv[node];
    float4 b = ((const float4*)bias)[lane];
    float4 o;
    o.x = fmaxf(fmaf(d, acc.x, b.x), 0.f);
    o.y = fmaxf(fmaf(d, acc.y, b.y), 0.f);
    o.z = fmaxf(fmaf(d, acc.z, b.z), 0.f);
    o.w = fmaxf(fmaf(d, acc.w, b.w), 0.f);

    // bn2 stats: reduce across the 16 node-groups
    __shared__ float4 rs[256], rq[256];
    __shared__ float s_a[64], s_c[64];
    __shared__ bool isLast;
    rs[tid] = o; rq[tid] = f4sq(o);
    __syncthreads();
    if (tid < 128) { rs[tid] = f4add(rs[tid], rs[tid + 128]); rq[tid] = f4add(rq[tid], rq[tid + 128]); }
    __syncthreads();
    if (tid < 64)  { rs[tid] = f4add(rs[tid], rs[tid + 64]);  rq[tid] = f4add(rq[tid], rq[tid + 64]); }
    __syncthreads();
    if (tid < 32)  { rs[tid] = f4add(rs[tid], rs[tid + 32]);  rq[tid] = f4add(rq[tid], rq[tid + 32]); }
    __syncthreads();
    if (tid < 16) {
        float4 s4 = f4add(rs[tid], rs[tid + 16]);
        float4 q4 = f4add(rq[tid], rq[tid + 16]);
        atomicAdd(&g_bnsum[128 + tid * 4 + 0], s4.x); atomicAdd(&g_bnsum[128 + tid * 4 + 1], s4.y);
        atomicAdd(&g_bnsum[128 + tid * 4 + 2], s4.z); atomicAdd(&g_bnsum[128 + tid * 4 + 3], s4.w);
        atomicAdd(&g_bnsq[128 + tid * 4 + 0], q4.x);  atomicAdd(&g_bnsq[128 + tid * 4 + 1], q4.y);
        atomicAdd(&g_bnsq[128 + tid * 4 + 2], q4.z);  atomicAdd(&g_bnsq[128 + tid * 4 + 3], q4.w);
    }

    // pool: warp-pair merge (two nodes per warp; batch sorted -> usually same graph)
    int bg = batch[node];
    int bo = __shfl_xor_sync(0xffffffffu, bg, 16);
    float4 po = o;
    float4 other;
    other.x = __shfl_xor_sync(0xffffffffu, o.x, 16);
    other.y = __shfl_xor_sync(0xffffffffu, o.y, 16);
    other.z = __shfl_xor_sync(0xffffffffu, o.z, 16);
    other.w = __shfl_xor_sync(0xffffffffu, o.w, 16);
    bool lower = ((tid & 31) < 16);
    bool same = (bg == bo);
    if (same && lower) po = f4add(po, other);
    if (!same || lower) {
        atomicAdd(&g_pool[bg * 64 + lane * 4 + 0], po.x);
        atomicAdd(&g_pool[bg * 64 + lane * 4 + 1], po.y);
        atomicAdd(&g_pool[bg * 64 + lane * 4 + 2], po.z);
        atomicAdd(&g_pool[bg * 64 + lane * 4 + 3], po.w);
    }

    __threadfence();
    __syncthreads();
    if (tid == 0) isLast = (atomicAdd(&g_ctr[1], 1) == (int)gridDim.x - 1);
    __syncthreads();
    if (!isLast) return;

    // bn2 finalize (affine folded: applied to pooled means)
    if (tid < 64) {
        float mean = g_bnsum[128 + tid] * (1.0f / NN);
        float var = g_bnsq[128 + tid] * (1.0f / NN) - mean * mean;
        float aa = gamma2[tid] * rsqrtf(var + EPSV);
        s_a[tid] = aa;
        s_c[tid] = beta2[tid] - mean * aa;
    }
    __syncthreads();
    // FC head: out[g, cl] = sum_j bn2(pool[g,j]/cnt[g]) * Wfc[j,cl] + bfc[cl]
    for (int t2 = tid; t2 < NG * 6; t2 += 256) {
        int gg = t2 / 6, cl = t2 % 6;
        float inv = 1.f / fmaxf((float)g_cnt[gg], 1.f);
        float accf = bfc[cl];
        #pragma unroll
        for (int j = 0; j < 64; j++) {
            float p = fmaf(s_a[j], g_pool[gg * 64 + j] * inv, s_c[j]);
            accf = fmaf(p, Wfc[j * 6 + cl], accf);
        }
        outp[gg * 6 + cl] = accf;
    }
}

// ---------------- host orchestration ----------------
extern "C" void kernel_launch(void* const* d_in, const int* in_sizes, int n_in,
                              void* d_out, int out_size) {
    const float* x      = (const float*)d_in[0];
    const int*   edge   = (const int*)d_in[1];
    const int*   batch  = (const int*)d_in[2];
    const float* W1     = (const float*)d_in[3];
    const float* b1     = (const float*)d_in[4];
    const float* W2     = (const float*)d_in[5];
    const float* b2     = (const float*)d_in[6];
    const float* gamma1 = (const float*)d_in[7];
    const float* beta1  = (const float*)d_in[8];
    const float* W3     = (const float*)d_in[9];
    const float* b3     = (const float*)d_in[10];
    const float* gamma2 = (const float*)d_in[11];
    const float* beta2  = (const float*)d_in[12];
    const float* Wfc    = (const float*)d_in[13];
    const float* bfc    = (const float*)d_in[14];
    float* out = (float*)d_out;

    const int* srcp = edge;
    const int* dstp = edge + NE;

    float *bufA, *bufB, *dinv, *aArr, *cArr;
    cudaGetSymbolAddress((void**)&bufA, g_bufA);
    cudaGetSymbolAddress((void**)&bufB, g_bufB);
    cudaGetSymbolAddress((void**)&dinv, g_dinv);
    cudaGetSymbolAddress((void**)&aArr, g_a);
    cudaGetSymbolAddress((void**)&cArr, g_c);

    // graph preprocessing
    zero_kernel<<<(NN + 255) / 256, 256>>>();
    count_kernel<<<(NE / 2 + 255) / 256, 256>>>(dstp);
    scan_kernel<<<1, 1024>>>();
    prep_kernel<<<(NN + 255) / 256, 256>>>(batch);
    fill_kernel<<<(NE / 2 + 255) / 256, 256>>>(srcp, dstp);

    // layer 1: xa = Â x (width 5), h1 = relu(xa @ W1 + b1)
    agg0_kernel<<<(NN * 5 + 255) / 256, 256>>>(x, bufA);
    gemm1_kernel<<<(NN * 64 + 255) / 256, 256>>>(bufA, W1, b1, bufB);

    // layer 2: u2 = dinv*(h1 @ W2) -> bufA; agg+relu+bn1stats -> h2 -> bufB
    gemm_tf32_kernel<128, 128, 32, 32, 64><<<dim3(1, (NN + 127) / 128), 256>>>(
        bufB, W2, bufA, NN, 256, 128, nullptr, nullptr, dinv);
    agg128_bn_kernel<<<NN / 8, 256>>>(bufA, b2, bufB, gamma1, beta1);

    // layer 3: bn1 folded into A-load; u3 = dinv*(bn1(h2) @ W3) -> bufA;
    // terminal agg: bn2 stats + pool + FC (h3 never materialized)
    gemm_tf32_kernel<128, 64, 32, 32, 64><<<dim3(1, (NN + 127) / 128), 128>>>(
        bufB, W3, bufA, NN, 128, 64, aArr, cArr, dinv);
    agg64_final_kernel<<<NN / 16, 256>>>(bufA, b3, batch, gamma2, beta2, Wfc, bfc, out);
}

// round 8
// speedup vs baseline: 2.6753x; 2.6753x over previous
#include <cuda_runtime.h>
#include <cstdint>

#define NN 50000
#define NE 800000
#define NG 64
#define EPSV 1e-5f

// ---------------- scratch (device globals; no allocations allowed) ----------------
__device__ float g_bufA[NN * 256];
__device__ float g_bufB[NN * 256];
__device__ float g_dinv[NN];
__device__ __align__(16) int g_deg[NN + 8];
__device__ __align__(16) int g_rowstart[NN + 8];
__device__ int   g_fill[NN];
__device__ int   g_csr[NE];
__device__ float g_a[128];            // bn1 scale
__device__ float g_c[128];            // bn1 shift
__device__ float g_bn1part[64][256];  // [slice][0:128 sum, 128:256 sq]
__device__ float g_bn2part[64][128];  // [slice][0:64 sum, 64:128 sq]
__device__ float g_poolpart[8][NG * 64];
__device__ int   g_ctr[4];

// ---------------- TF32 helpers ----------------
__device__ __forceinline__ unsigned cvt_tf32(float v) {
    unsigned r;
    asm("cvt.rna.tf32.f32 %0, %1;" : "=r"(r) : "f"(v));
    return r;
}
__device__ __forceinline__ void mma_tf32(float* c, const unsigned* a, const unsigned* b) {
    asm volatile(
        "mma.sync.aligned.m16n8k8.row.col.f32.tf32.tf32.f32 "
        "{%0,%1,%2,%3}, {%4,%5,%6,%7}, {%8,%9}, {%0,%1,%2,%3};"
        : "+f"(c[0]), "+f"(c[1]), "+f"(c[2]), "+f"(c[3])
        : "r"(a[0]), "r"(a[1]), "r"(a[2]), "r"(a[3]), "r"(b[0]), "r"(b[1]));
}

__device__ __forceinline__ float4 f4add(float4 a, float4 b) {
    return make_float4(a.x + b.x, a.y + b.y, a.z + b.z, a.w + b.w);
}
__device__ __forceinline__ float4 f4sq(float4 a) {
    return make_float4(a.x * a.x, a.y * a.y, a.z * a.z, a.w * a.w);
}

// ---------------- setup kernels ----------------
__global__ void zero_kernel() {
    int i = blockIdx.x * 256 + threadIdx.x;
    if (i < NN) g_deg[i] = 0;
    if (i < 64 * 256) ((float*)g_bn1part)[i] = 0.f;
    if (i < 64 * 128) ((float*)g_bn2part)[i] = 0.f;
    if (i < 8 * NG * 64) ((float*)g_poolpart)[i] = 0.f;
    if (i < 4) g_ctr[i] = 0;
}

__global__ void count_kernel(const int* __restrict__ dst) {
    int e = (blockIdx.x * 256 + threadIdx.x) * 2;
    if (e < NE) {
        int2 d = *(const int2*)&dst[e];
        atomicAdd(&g_deg[d.x], 1);
        atomicAdd(&g_deg[d.y], 1);
    }
}

// Single-block exclusive scan over degrees -> rowstart (int4-vectorized).
__global__ void scan_kernel() {
    const int CH = 52;
    int tid = threadIdx.x;
    int lo = tid * CH; if (lo > NN) lo = NN;
    int hi = lo + CH;  if (hi > NN) hi = NN;
    int s = 0;
    for (int i = lo; i < hi; i += 4) {
        int4 d = *(const int4*)&g_deg[i];
        s += d.x + d.y + d.z + d.w;
    }
    __shared__ int warpsum[32];
    int lane = tid & 31, wid = tid >> 5;
    int incl = s;
    #pragma unroll
    for (int o = 1; o < 32; o <<= 1) {
        int v = __shfl_up_sync(0xffffffffu, incl, o);
        if (lane >= o) incl += v;
    }
    if (lane == 31) warpsum[wid] = incl;
    __syncthreads();
    if (wid == 0) {
        int w = warpsum[lane];
        int wincl = w;
        #pragma unroll
        for (int o = 1; o < 32; o <<= 1) {
            int v = __shfl_up_sync(0xffffffffu, wincl, o);
            if (lane >= o) wincl += v;
        }
        warpsum[lane] = wincl - w;
    }
    __syncthreads();
    int run = (incl - s) + warpsum[wid];
    for (int i = lo; i < hi; i += 4) {
        int4 d = *(const int4*)&g_deg[i];
        int4 rs;
        rs.x = run;
        rs.y = run + d.x;
        rs.z = run + d.x + d.y;
        rs.w = run + d.x + d.y + d.z;
        run += d.x + d.y + d.z + d.w;
        *(int4*)&g_rowstart[i] = rs;
    }
    if (lo < NN && hi == NN) g_rowstart[NN] = run;
}

// full-chip: dinv + fill cursors (NO per-graph atomics — counts done by binary search later)
__global__ void prep_kernel() {
    int i = blockIdx.x * 256 + threadIdx.x;
    if (i < NN) {
        g_dinv[i] = rsqrtf((float)(g_deg[i] + 1));
        g_fill[i] = 0;
    }
}

__global__ void fill_kernel(const int* __restrict__ src, const int* __restrict__ dst) {
    int e = (blockIdx.x * 256 + threadIdx.x) * 2;
    if (e < NE) {
        int2 d = *(const int2*)&dst[e];
        int2 sc = *(const int2*)&src[e];
        int p0 = g_rowstart[d.x] + atomicAdd(&g_fill[d.x], 1);
        g_csr[p0] = sc.x;
        int p1 = g_rowstart[d.y] + atomicAdd(&g_fill[d.y], 1);
        g_csr[p1] = sc.y;
    }
}

// ---------------- layer-1 input aggregation (width 5) ----------------
__global__ void agg0_kernel(const float* __restrict__ x, float* __restrict__ xa) {
    int t = blockIdx.x * 256 + threadIdx.x;
    if (t >= NN * 5) return;
    int node = t / 5, f = t - node * 5;
    float dn = g_dinv[node];
    float acc = x[t] * dn;
    int s = g_rowstart[node], e = g_rowstart[node + 1];
    for (int j = s; j < e; j++) {
        int src = g_csr[j];
        acc += __ldg(&x[src * 5 + f]) * __ldg(&g_dinv[src]);
    }
    xa[t] = dn * acc;
}

// h1 = relu(xa @ W1 + b1), [N,5] -> [N,256]
__global__ void gemm1_kernel(const float* __restrict__ xa, const float* __restrict__ W1,
                             const float* __restrict__ b1, float* __restrict__ h1) {
    __shared__ float w[5 * 256];
    __shared__ float bs[256];
    for (int i = threadIdx.x; i < 1280; i += 256) w[i] = W1[i];
    bs[threadIdx.x] = b1[threadIdx.x];
    __syncthreads();
    int idx = blockIdx.x * 256 + threadIdx.x;
    if (idx >= NN * 64) return;
    int node = idx >> 6;
    int c = (idx & 63) * 4;
    float xv[5];
    #pragma unroll
    for (int k = 0; k < 5; k++) xv[k] = xa[node * 5 + k];
    float4 acc = make_float4(bs[c], bs[c + 1], bs[c + 2], bs[c + 3]);
    #pragma unroll
    for (int k = 0; k < 5; k++) {
        acc.x = fmaf(xv[k], w[k * 256 + c + 0], acc.x);
        acc.y = fmaf(xv[k], w[k * 256 + c + 1], acc.y);
        acc.z = fmaf(xv[k], w[k * 256 + c + 2], acc.z);
        acc.w = fmaf(xv[k], w[k * 256 + c + 3], acc.w);
    }
    acc.x = fmaxf(acc.x, 0.f); acc.y = fmaxf(acc.y, 0.f);
    acc.z = fmaxf(acc.z, 0.f); acc.w = fmaxf(acc.w, 0.f);
    ((float4*)h1)[idx] = acc;
}

// ---------------- TF32 tensor-core GEMM ----------------
template <int BM, int BN, int BK, int WM, int WN>
__global__ void gemm_tf32_kernel(const float* __restrict__ A, const float* __restrict__ W,
                                 float* __restrict__ out, int M, int K, int N,
                                 const float* __restrict__ affA, const float* __restrict__ affC,
                                 const float* __restrict__ rowscale) {
    constexpr int WARPS_M = BM / WM;
    constexpr int WARPS_N = BN / WN;
    constexpr int THREADS = WARPS_M * WARPS_N * 32;
    constexpr int MT = WM / 16;
    constexpr int NT = WN / 8;

    __shared__ unsigned As[BK][BM + 4];
    __shared__ unsigned Bs[BK][BN + 4];

    int tid = threadIdx.x;
    int lane = tid & 31;
    int wid = tid >> 5;
    int warpM = wid % WARPS_M;
    int warpN = wid / WARPS_M;
    int g = lane >> 2;
    int t = lane & 3;
    int rowBase = blockIdx.y * BM;
    int colBase = blockIdx.x * BN;

    float acc[MT][NT][4];
    #pragma unroll
    for (int i = 0; i < MT; i++)
        #pragma unroll
        for (int j = 0; j < NT; j++)
            #pragma unroll
            for (int q = 0; q < 4; q++) acc[i][j][q] = 0.f;

    for (int k0 = 0; k0 < K; k0 += BK) {
        #pragma unroll
        for (int it = tid; it < BM * BK / 4; it += THREADS) {
            int m = it / (BK / 4);
            int kq = (it % (BK / 4)) * 4;
            int gr = rowBase + m;
            float4 v = make_float4(0.f, 0.f, 0.f, 0.f);
            if (gr < M) {
                v = *(const float4*)&A[gr * K + k0 + kq];
                if (affA) {
                    v.x = fmaf(v.x, affA[k0 + kq + 0], affC[k0 + kq + 0]);
                    v.y = fmaf(v.y, affA[k0 + kq + 1], affC[k0 + kq + 1]);
                    v.z = fmaf(v.z, affA[k0 + kq + 2], affC[k0 + kq + 2]);
                    v.w = fmaf(v.w, affA[k0 + kq + 3], affC[k0 + kq + 3]);
                }
            }
            As[kq + 0][m] = cvt_tf32(v.x);
            As[kq + 1][m] = cvt_tf32(v.y);
            As[kq + 2][m] = cvt_tf32(v.z);
            As[kq + 3][m] = cvt_tf32(v.w);
        }
        #pragma unroll
        for (int it = tid; it < BK * BN / 4; it += THREADS) {
            int k = it / (BN / 4);
            int nq = (it % (BN / 4)) * 4;
            float4 v = *(const float4*)&W[(k0 + k) * N + colBase + nq];
            Bs[k][nq + 0] = cvt_tf32(v.x);
            Bs[k][nq + 1] = cvt_tf32(v.y);
            Bs[k][nq + 2] = cvt_tf32(v.z);
            Bs[k][nq + 3] = cvt_tf32(v.w);
        }
        __syncthreads();
        #pragma unroll
        for (int kk = 0; kk < BK; kk += 8) {
            unsigned a[MT][4], b[NT][2];
            #pragma unroll
            for (int mt = 0; mt < MT; mt++) {
                int mb = warpM * WM + mt * 16;
                a[mt][0] = As[kk + t][mb + g];
                a[mt][1] = As[kk + t][mb + g + 8];
                a[mt][2] = As[kk + t + 4][mb + g];
                a[mt][3] = As[kk + t + 4][mb + g + 8];
            }
            #pragma unroll
            for (int nt = 0; nt < NT; nt++) {
                int nb = warpN * WN + nt * 8;
                b[nt][0] = Bs[kk + t][nb + g];
                b[nt][1] = Bs[kk + t + 4][nb + g];
            }
            #pragma unroll
            for (int mt = 0; mt < MT; mt++)
                #pragma unroll
                for (int nt = 0; nt < NT; nt++)
                    mma_tf32(acc[mt][nt], a[mt], b[nt]);
        }
        __syncthreads();
    }

    #pragma unroll
    for (int mt = 0; mt < MT; mt++) {
        int r0 = rowBase + warpM * WM + mt * 16 + g;
        int r1 = r0 + 8;
        float rs0 = (r0 < M) ? (rowscale ? rowscale[r0] : 1.f) : 0.f;
        float rs1 = (r1 < M) ? (rowscale ? rowscale[r1] : 1.f) : 0.f;
        #pragma unroll
        for (int nt = 0; nt < NT; nt++) {
            int col = colBase + warpN * WN + nt * 8 + 2 * t;
            if (r0 < M) {
                float2 v = make_float2(acc[mt][nt][0] * rs0, acc[mt][nt][1] * rs0);
                *(float2*)&out[r0 * N + col] = v;
            }
            if (r1 < M) {
                float2 v = make_float2(acc[mt][nt][2] * rs1, acc[mt][nt][3] * rs1);
                *(float2*)&out[r1 * N + col] = v;
            }
        }
    }
}

// ---------------- agg core: 4-chain CSR gather ----------------
template <int CH>
__device__ __forceinline__ float4 agg_gather(const float4* __restrict__ u4,
                                             int node, int lane) {
    float4 a0 = u4[node * CH + lane];   // self-loop
    float4 a1 = make_float4(0.f, 0.f, 0.f, 0.f);
    float4 a2 = make_float4(0.f, 0.f, 0.f, 0.f);
    float4 a3 = make_float4(0.f, 0.f, 0.f, 0.f);
    int s = g_rowstart[node];
    int e = g_rowstart[node + 1];
    int j = s;
    for (; j + 4 <= e; j += 4) {
        int s0 = __ldg(&g_csr[j]);
        int s1 = __ldg(&g_csr[j + 1]);
        int s2 = __ldg(&g_csr[j + 2]);
        int s3 = __ldg(&g_csr[j + 3]);
        float4 v0 = __ldg(&u4[s0 * CH + lane]);
        float4 v1 = __ldg(&u4[s1 * CH + lane]);
        float4 v2 = __ldg(&u4[s2 * CH + lane]);
        float4 v3 = __ldg(&u4[s3 * CH + lane]);
        a0 = f4add(a0, v0); a1 = f4add(a1, v1);
        a2 = f4add(a2, v2); a3 = f4add(a3, v3);
    }
    for (; j < e; j++) {
        float4 v = __ldg(&u4[__ldg(&g_csr[j]) * CH + lane]);
        a0 = f4add(a0, v);
    }
    return f4add(f4add(a0, a1), f4add(a2, a3));
}

// ---------------- agg<128> + bn1 partial stats (sliced) + finalize (last block) ----------------
__global__ void agg128_bn_kernel(const float* __restrict__ u, const float* __restrict__ bias,
                                 float* __restrict__ out,
                                 const float* __restrict__ gamma, const float* __restrict__ beta) {
    constexpr int CH = 32;
    int tid = threadIdx.x;
    int node = blockIdx.x * 8 + (tid >> 5);   // NN % 8 == 0
    int lane = tid & 31;
    const float4* u4 = (const float4*)u;
    float4 acc = agg_gather<CH>(u4, node, lane);
    float d = g_dinv[node];
    float4 b = ((const float4*)bias)[lane];
    float4 o;
    o.x = fmaxf(fmaf(d, acc.x, b.x), 0.f);
    o.y = fmaxf(fmaf(d, acc.y, b.y), 0.f);
    o.z = fmaxf(fmaf(d, acc.z, b.z), 0.f);
    o.w = fmaxf(fmaf(d, acc.w, b.w), 0.f);
    ((float4*)out)[node * CH + lane] = o;

    // block-reduce bn sums across the 8 node-warps
    __shared__ float4 rs[256], rq[256];
    __shared__ bool isLast;
    rs[tid] = o; rq[tid] = f4sq(o);
    __syncthreads();
    if (tid < 128) { rs[tid] = f4add(rs[tid], rs[tid + 128]); rq[tid] = f4add(rq[tid], rq[tid + 128]); }
    __syncthreads();
    if (tid < 64)  { rs[tid] = f4add(rs[tid], rs[tid + 64]);  rq[tid] = f4add(rq[tid], rq[tid + 64]); }
    __syncthreads();
    int slice = blockIdx.x & 63;
    if (tid < 32) {
        float4 s4 = f4add(rs[tid], rs[tid + 32]);
        float4 q4 = f4add(rq[tid], rq[tid + 32]);
        float* ps = &g_bn1part[slice][tid * 4];
        float* pq = &g_bn1part[slice][128 + tid * 4];
        atomicAdd(&ps[0], s4.x); atomicAdd(&ps[1], s4.y);
        atomicAdd(&ps[2], s4.z); atomicAdd(&ps[3], s4.w);
        atomicAdd(&pq[0], q4.x); atomicAdd(&pq[1], q4.y);
        atomicAdd(&pq[2], q4.z); atomicAdd(&pq[3], q4.w);
    }
    __threadfence();
    __syncthreads();
    if (tid == 0) isLast = (atomicAdd(&g_ctr[0], 1) == (int)gridDim.x - 1);
    __syncthreads();
    if (isLast && tid < 128) {
        float sum = 0.f, sq = 0.f;
        #pragma unroll 8
        for (int s2 = 0; s2 < 64; s2++) {
            sum += g_bn1part[s2][tid];
            sq  += g_bn1part[s2][128 + tid];
        }
        float mean = sum * (1.0f / NN);
        float var = sq * (1.0f / NN) - mean * mean;
        float aa = gamma[tid] * rsqrtf(var + EPSV);
        g_a[tid] = aa;
        g_c[tid] = beta[tid] - mean * aa;
    }
}

// ---------------- agg<64> terminal: bn2 partials + pool partials + FC head ----------------
__device__ __forceinline__ int lower_bound_i(const int* arr, int n, int val) {
    int lo = 0, hi = n;
    while (lo < hi) {
        int mid = (lo + hi) >> 1;
        if (arr[mid] < val) lo = mid + 1; else hi = mid;
    }
    return lo;
}

__global__ void agg64_final_kernel(const float* __restrict__ u, const float* __restrict__ bias,
                                   const int* __restrict__ batch,
                                   const float* __restrict__ gamma2, const float* __restrict__ beta2,
                                   const float* __restrict__ Wfc, const float* __restrict__ bfc,
                                   float* __restrict__ outp) {
    constexpr int CH = 16;
    int tid = threadIdx.x;
    int node = blockIdx.x * 16 + (tid >> 4);   // NN % 16 == 0
    int lane = tid & 15;
    const float4* u4 = (const float4*)u;
    float4 acc = agg_gather<CH>(u4, node, lane);
    float d = g_dinv[node];
    float4 b = ((const float4*)bias)[lane];
    float4 o;
    o.x = fmaxf(fmaf(d, acc.x, b.x), 0.f);
    o.y = fmaxf(fmaf(d, acc.y, b.y), 0.f);
    o.z = fmaxf(fmaf(d, acc.z, b.z), 0.f);
    o.w = fmaxf(fmaf(d, acc.w, b.w), 0.f);

    // bn2 stats: block reduce then sliced atomics
    __shared__ float4 rs[256], rq[256];
    __shared__ float s_a[64], s_c[64];
    __shared__ float pooled[NG * 64];
    __shared__ int s_cnt[NG];
    __shared__ bool isLast;
    rs[tid] = o; rq[tid] = f4sq(o);
    __syncthreads();
    if (tid < 128) { rs[tid] = f4add(rs[tid], rs[tid + 128]); rq[tid] = f4add(rq[tid], rq[tid + 128]); }
    __syncthreads();
    if (tid < 64)  { rs[tid] = f4add(rs[tid], rs[tid + 64]);  rq[tid] = f4add(rq[tid], rq[tid + 64]); }
    __syncthreads();
    if (tid < 32)  { rs[tid] = f4add(rs[tid], rs[tid + 32]);  rq[tid] = f4add(rq[tid], rq[tid + 32]); }
    __syncthreads();
    int slice = blockIdx.x & 63;
    if (tid < 16) {
        float4 s4 = f4add(rs[tid], rs[tid + 16]);
        float4 q4 = f4add(rq[tid], rq[tid + 16]);
        float* ps = &g_bn2part[slice][tid * 4];
        float* pq = &g_bn2part[slice][64 + tid * 4];
        atomicAdd(&ps[0], s4.x); atomicAdd(&ps[1], s4.y);
        atomicAdd(&ps[2], s4.z); atomicAdd(&ps[3], s4.w);
        atomicAdd(&pq[0], q4.x); atomicAdd(&pq[1], q4.y);
        atomicAdd(&pq[2], q4.z); atomicAdd(&pq[3], q4.w);
    }

    // pool: warp-pair merge, then sliced atomics (8 replicas)
    int bg = batch[node];
    int bo = __shfl_xor_sync(0xffffffffu, bg, 16);
    float4 po = o;
    float4 other;
    other.x = __shfl_xor_sync(0xffffffffu, o.x, 16);
    other.y = __shfl_xor_sync(0xffffffffu, o.y, 16);
    other.z = __shfl_xor_sync(0xffffffffu, o.z, 16);
    other.w = __shfl_xor_sync(0xffffffffu, o.w, 16);
    bool lower = ((tid & 31) < 16);
    bool same = (bg == bo);
    if (same && lower) po = f4add(po, other);
    if (!same || lower) {
        float* pp = &g_poolpart[blockIdx.x & 7][bg * 64 + lane * 4];
        atomicAdd(&pp[0], po.x); atomicAdd(&pp[1], po.y);
        atomicAdd(&pp[2], po.z); atomicAdd(&pp[3], po.w);
    }

    __threadfence();
    __syncthreads();
    if (tid == 0) isLast = (atomicAdd(&g_ctr[1], 1) == (int)gridDim.x - 1);
    __syncthreads();
    if (!isLast) return;

    // ---- last block: finalize bn2, counts, pool reduce, FC head ----
    if (tid < 64) {
        float sum = 0.f, sq = 0.f;
        #pragma unroll 8
        for (int s2 = 0; s2 < 64; s2++) {
            sum += g_bn2part[s2][tid];
            sq  += g_bn2part[s2][64 + tid];
        }
        float mean = sum * (1.0f / NN);
        float var = sq * (1.0f / NN) - mean * mean;
        float aa = gamma2[tid] * rsqrtf(var + EPSV);
        s_a[tid] = aa;
        s_c[tid] = beta2[tid] - mean * aa;
    }
    if (tid >= 64 && tid < 64 + NG) {
        int gg = tid - 64;
        s_cnt[gg] = lower_bound_i(batch, NN, gg + 1) - lower_bound_i(batch, NN, gg);
    }
    __syncthreads();
    // pool reduce across 8 slices + bn2 affine on the mean
    for (int i = tid; i < NG * 64; i += 256) {
        float sum = 0.f;
        #pragma unroll
        for (int s2 = 0; s2 < 8; s2++) sum += g_poolpart[s2][i];
        int gg = i >> 6, j = i & 63;
        float inv = 1.f / fmaxf((float)s_cnt[gg], 1.f);
        pooled[i] = fmaf(s_a[j], sum * inv, s_c[j]);
    }
    __syncthreads();
    // FC head
    for (int t2 = tid; t2 < NG * 6; t2 += 256) {
        int gg = t2 / 6, cl = t2 % 6;
        float accf = bfc[cl];
        #pragma unroll
        for (int j = 0; j < 64; j++)
            accf = fmaf(pooled[gg * 64 + j], Wfc[j * 6 + cl], accf);
        outp[gg * 6 + cl] = accf;
    }
}

// ---------------- host orchestration ----------------
extern "C" void kernel_launch(void* const* d_in, const int* in_sizes, int n_in,
                              void* d_out, int out_size) {
    const float* x      = (const float*)d_in[0];
    const int*   edge   = (const int*)d_in[1];
    const int*   batch  = (const int*)d_in[2];
    const float* W1     = (const float*)d_in[3];
    const float* b1     = (const float*)d_in[4];
    const float* W2     = (const float*)d_in[5];
    const float* b2     = (const float*)d_in[6];
    const float* gamma1 = (const float*)d_in[7];
    const float* beta1  = (const float*)d_in[8];
    const float* W3     = (const float*)d_in[9];
    const float* b3     = (const float*)d_in[10];
    const float* gamma2 = (const float*)d_in[11];
    const float* beta2  = (const float*)d_in[12];
    const float* Wfc    = (const float*)d_in[13];
    const float* bfc    = (const float*)d_in[14];
    float* out = (float*)d_out;

    const int* srcp = edge;
    const int* dstp = edge + NE;

    float *bufA, *bufB, *dinv, *aArr, *cArr;
    cudaGetSymbolAddress((void**)&bufA, g_bufA);
    cudaGetSymbolAddress((void**)&bufB, g_bufB);
    cudaGetSymbolAddress((void**)&dinv, g_dinv);
    cudaGetSymbolAddress((void**)&aArr, g_a);
    cudaGetSymbolAddress((void**)&cArr, g_c);

    // graph preprocessing
    zero_kernel<<<(NN + 255) / 256, 256>>>();
    count_kernel<<<(NE / 2 + 255) / 256, 256>>>(dstp);
    scan_kernel<<<1, 1024>>>();
    prep_kernel<<<(NN + 255) / 256, 256>>>();
    fill_kernel<<<(NE / 2 + 255) / 256, 256>>>(srcp, dstp);

    // layer 1: xa = Â x (width 5), h1 = relu(xa @ W1 + b1)
    agg0_kernel<<<(NN * 5 + 255) / 256, 256>>>(x, bufA);
    gemm1_kernel<<<(NN * 64 + 255) / 256, 256>>>(bufA, W1, b1, bufB);

    // layer 2: u2 = dinv*(h1 @ W2) -> bufA; agg+relu+bn1 stats -> h2 -> bufB
    gemm_tf32_kernel<128, 128, 32, 32, 64><<<dim3(1, (NN + 127) / 128), 256>>>(
        bufB, W2, bufA, NN, 256, 128, nullptr, nullptr, dinv);
    agg128_bn_kernel<<<NN / 8, 256>>>(bufA, b2, bufB, gamma1, beta1);

    // layer 3: bn1 folded; u3 = dinv*(bn1(h2) @ W3) -> bufA; terminal agg (h3 never stored)
    gemm_tf32_kernel<128, 64, 32, 32, 64><<<dim3(1, (NN + 127) / 128), 128>>>(
        bufB, W3, bufA, NN, 128, 64, aArr, cArr, dinv);
    agg64_final_kernel<<<NN / 16, 256>>>(bufA, b3, batch, gamma2, beta2, Wfc, bfc, out);
}